// round 1
// baseline (speedup 1.0000x reference)
#include <cuda_runtime.h>

#define NB    128
#define CIN   8
#define HIN   128
#define WIN   128
#define COUT  64
#define HO    126
#define WO    126
#define PHN   31
#define PWN   31
#define NG    16
#define CPG   4   // channels per group

// Scratch (static device globals — no runtime allocation)
__device__ float  g_smax[(size_t)NB * COUT * PHN * PWN];   // 31.5 MB
__device__ float  g_smin[(size_t)NB * COUT * PHN * PWN];   // 31.5 MB
__device__ float2 g_partial[32 * NB * NG];                 // per (row-group, b, g) {sum, sumsq}
__device__ float2 g_stats[NB * NG];                        // {mean, rstd}

// ---------------------------------------------------------------------------
// Pass 1: conv + bias; per-window max/min; per-(b,g) partial stats.
// Grid: (32 row-groups, 128 batches), block = 256 threads.
// Thread t: wx = t&31 (window col / edge cols), cb = t>>5 (8-channel block).
// Warp == one cb, so groups 2*cb, 2*cb+1 belong exclusively to one warp.
// ---------------------------------------------------------------------------
__global__ __launch_bounds__(256) void conv_pass1(const float* __restrict__ x,
                                                  const float* __restrict__ w,
                                                  const float* __restrict__ bias)
{
    const int pr = blockIdx.x;   // 0..31 ; pr<31: 4 output rows; pr==31: rows 124,125 (stats only)
    const int b  = blockIdx.y;
    const int t  = threadIdx.x;

    __shared__ float xs[CIN][6][132];   // 6 input rows, 128 cols + 4 zero-pad
    __shared__ float wsm[72][64];       // [cin*9+ky*3+kx][co]
    __shared__ float bsm[64];

    // weights: global layout [co][cin][ky][kx]
    for (int i = t; i < 64 * 72; i += 256) {
        int co = i / 72, k = i % 72;
        wsm[k][co] = w[i];
    }
    if (t < 64) bsm[t] = bias[t];

    const int h0 = pr * 4;
    // x tile: rows h0..h0+5 (guarded), all 128 cols, 8 channels; float4 loads
    for (int i = t; i < CIN * 6 * 32; i += 256) {
        int c4 = i & 31;
        int rr = (i >> 5) % 6;
        int cin = i / (6 * 32);
        int h = h0 + rr;
        float4 v = make_float4(0.f, 0.f, 0.f, 0.f);
        if (h < HIN)
            v = *(const float4*)&x[(((size_t)b * CIN + cin) * HIN + h) * WIN + c4 * 4];
        *(float4*)&xs[cin][rr][c4 * 4] = v;
    }
    if (t < CIN * 6) {
        int rr = t % 6, cin = t / 6;
        *(float4*)&xs[cin][rr][128] = make_float4(0.f, 0.f, 0.f, 0.f);
    }
    __syncthreads();

    const int wx   = t & 31;
    const int cb   = t >> 5;
    const int col0 = wx * 4;
    const int R    = (pr == 31) ? 2 : 4;

    float wmax[8], wmin[8];
#pragma unroll
    for (int j = 0; j < 8; j++) { wmax[j] = -1e30f; wmin[j] = 1e30f; }
    float s0 = 0.f, q0 = 0.f, s1 = 0.f, q1 = 0.f;

    for (int r = 0; r < R; r++) {
        float acc[8][4];
#pragma unroll
        for (int j = 0; j < 8; j++)
#pragma unroll
            for (int c = 0; c < 4; c++) acc[j][c] = 0.f;

#pragma unroll
        for (int cin = 0; cin < 8; cin++) {
#pragma unroll
            for (int ky = 0; ky < 3; ky++) {
                const float* xr = &xs[cin][r + ky][col0];
                float xv0 = xr[0], xv1 = xr[1], xv2 = xr[2];
                float xv3 = xr[3], xv4 = xr[4], xv5 = xr[5];
                const float* wp = &wsm[cin * 9 + ky * 3][cb * 8];
#pragma unroll
                for (int j = 0; j < 8; j++) {
                    float w0 = wp[j], w1 = wp[64 + j], w2 = wp[128 + j];
                    acc[j][0] = fmaf(w0, xv0, fmaf(w1, xv1, fmaf(w2, xv2, acc[j][0])));
                    acc[j][1] = fmaf(w0, xv1, fmaf(w1, xv2, fmaf(w2, xv3, acc[j][1])));
                    acc[j][2] = fmaf(w0, xv2, fmaf(w1, xv3, fmaf(w2, xv4, acc[j][2])));
                    acc[j][3] = fmaf(w0, xv3, fmaf(w1, xv4, fmaf(w2, xv5, acc[j][3])));
                }
            }
        }

        // bias + stats + window min/max
#pragma unroll
        for (int j = 0; j < 8; j++) {
            float bb = bsm[cb * 8 + j];
            float v0 = acc[j][0] + bb, v1 = acc[j][1] + bb;
            float v2 = acc[j][2] + bb, v3 = acc[j][3] + bb;
            float sum, sq;
            if (wx < 31) {                      // cols col0..col0+3 all < 126
                sum = (v0 + v1) + (v2 + v3);
                sq  = (v0 * v0 + v1 * v1) + (v2 * v2 + v3 * v3);
            } else {                            // cols 124,125 valid; 126,127 garbage
                sum = v0 + v1;
                sq  = v0 * v0 + v1 * v1;
            }
            if (j < 4) { s0 += sum; q0 += sq; } else { s1 += sum; q1 += sq; }

            float mx = fmaxf(fmaxf(v0, v1), fmaxf(v2, v3));
            float mn = fminf(fminf(v0, v1), fminf(v2, v3));
            wmax[j] = fmaxf(wmax[j], mx);
            wmin[j] = fminf(wmin[j], mn);
        }
    }

    // pooled window raw max/min (only real windows)
    if (pr < 31 && wx < 31) {
#pragma unroll
        for (int j = 0; j < 8; j++) {
            int co = cb * 8 + j;
            size_t o = (((size_t)b * COUT + co) * PHN + pr) * PWN + wx;
            g_smax[o] = wmax[j];
            g_smin[o] = wmin[j];
        }
    }

    // warp-level stats reduction; warp cb exclusively owns groups 2cb, 2cb+1
#pragma unroll
    for (int o = 16; o > 0; o >>= 1) {
        s0 += __shfl_down_sync(0xffffffffu, s0, o);
        q0 += __shfl_down_sync(0xffffffffu, q0, o);
        s1 += __shfl_down_sync(0xffffffffu, s1, o);
        q1 += __shfl_down_sync(0xffffffffu, q1, o);
    }
    if (wx == 0) {
        int base = (pr * NB + b) * NG + cb * 2;
        g_partial[base]     = make_float2(s0, q0);
        g_partial[base + 1] = make_float2(s1, q1);
    }
}

// ---------------------------------------------------------------------------
// Pass 2: fold 32 row-group partials into mean/rstd per (b, g). Deterministic.
// ---------------------------------------------------------------------------
__global__ void stats_pass2()
{
    int idx = blockIdx.x * 256 + threadIdx.x;   // b*16+g
    if (idx >= NB * NG) return;
    float s = 0.f, q = 0.f;
    for (int pr = 0; pr < 32; pr++) {
        float2 p = g_partial[pr * (NB * NG) + idx];
        s += p.x; q += p.y;
    }
    const float inv = 1.f / (float)(CPG * HO * WO);
    float mean = s * inv;
    float var  = q * inv - mean * mean;
    g_stats[idx] = make_float2(mean, rsqrtf(var + 1e-5f));
}

// ---------------------------------------------------------------------------
// Pass 3: per output element, affine-of-max/min + clamp.
// ---------------------------------------------------------------------------
__global__ void apply_pass3(const float* __restrict__ gnw,
                            const float* __restrict__ gnb,
                            const float* __restrict__ scale,
                            float* __restrict__ out, int n)
{
    int idx = blockIdx.x * 256 + threadIdx.x;
    if (idx >= n) return;
    int tmp = idx / PWN;           // drop pw
    tmp /= PHN;                    // drop ph
    int c = tmp % COUT;
    int b = tmp / COUT;

    float2 st = g_stats[b * NG + (c >> 2)];   // mean, rstd
    float gw = gnw[c], sc = scale[c];
    float A  = st.y * gw * sc;
    float Bt = (gnb[c] - st.x * st.y * gw) * sc;

    float y = (A >= 0.f) ? g_smax[idx] : g_smin[idx];
    float v = fmaf(A, y, Bt);
    out[idx] = fminf(fmaxf(v, 0.f), 1.f);
}

// ---------------------------------------------------------------------------
extern "C" void kernel_launch(void* const* d_in, const int* in_sizes, int n_in,
                              void* d_out, int out_size)
{
    const float* x     = (const float*)d_in[0];
    const float* w     = (const float*)d_in[1];
    const float* bias  = (const float*)d_in[2];
    const float* gnw   = (const float*)d_in[3];
    const float* gnb   = (const float*)d_in[4];
    const float* scale = (const float*)d_in[5];
    float* out = (float*)d_out;

    dim3 g1(32, NB);
    conv_pass1<<<g1, 256>>>(x, w, bias);
    stats_pass2<<<(NB * NG + 255) / 256, 256>>>();
    int n = NB * COUT * PHN * PWN;   // == out_size
    apply_pass3<<<(n + 255) / 256, 256>>>(gnw, gnb, scale, out, n);
}